// round 2
// baseline (speedup 1.0000x reference)
#include <cuda_runtime.h>
#include <cuda_bf16.h>

#define F 128
#define MAX_ATOMS 50000
#define PPW 64   // pairs per warp in scatter

// Scratch (device globals: no allocation allowed)
__device__ __align__(16) float g_A[MAX_ATOMS * F];   // segment_sum(alpha*x[idx_j]) result
__device__ __align__(16) float g_WT[F * F];          // W transposed: WT[k][n] = W[n][k]

// ---------------------------------------------------------------------------
// helpers
// ---------------------------------------------------------------------------
using u64 = unsigned long long;

__device__ __forceinline__ u64 pack2(float lo, float hi) {
    u64 r;
    asm("mov.b64 %0, {%1, %2};" : "=l"(r) : "f"(lo), "f"(hi));
    return r;
}
__device__ __forceinline__ void unpack2(u64 v, float& lo, float& hi) {
    asm("mov.b64 {%0, %1}, %2;" : "=f"(lo), "=f"(hi) : "l"(v));
}
__device__ __forceinline__ u64 fma2(u64 a, u64 b, u64 c) {
    u64 d;
    asm("fma.rn.f32x2 %0, %1, %2, %3;" : "=l"(d) : "l"(a), "l"(b), "l"(c));
    return d;
}
__device__ __forceinline__ void red_add_v4(float* addr, float4 v) {
    asm volatile("red.global.add.v4.f32 [%0], {%1, %2, %3, %4};"
                 :: "l"(addr), "f"(v.x), "f"(v.y), "f"(v.z), "f"(v.w) : "memory");
}

// ---------------------------------------------------------------------------
// kernel 0: zero the scatter accumulator
// ---------------------------------------------------------------------------
__global__ void zero_kernel(int n4) {
    float4* p = (float4*)g_A;
    float4 z = {0.f, 0.f, 0.f, 0.f};
    int stride = gridDim.x * blockDim.x;
    for (int i = blockIdx.x * blockDim.x + threadIdx.x; i < n4; i += stride)
        p[i] = z;
}

// ---------------------------------------------------------------------------
// kernel 1: transpose W (128x128, tiny)
// ---------------------------------------------------------------------------
__global__ void transpose_kernel(const float* __restrict__ W) {
    int idx = blockIdx.x * 256 + threadIdx.x;
    if (idx < F * F) {
        int n = idx >> 7;
        int k = idx & 127;
        g_WT[k * F + n] = W[idx];
    }
}

// ---------------------------------------------------------------------------
// kernel 2: scatter  A[i] += alpha_p * x[j]  for each pair p
// idx_i is sorted -> register run-accumulation, flush with red.global.add.v4
// One warp handles PPW consecutive pairs; lane l owns columns [4l, 4l+4).
// Indices are INT32 (jax demotes int64 with x64 disabled).
// ---------------------------------------------------------------------------
__global__ void scatter_kernel(const float* __restrict__ x,
                               const float* __restrict__ alpha,
                               const int* __restrict__ idx_i,
                               const int* __restrict__ idx_j,
                               int n_pairs, int n_atoms) {
    __shared__ int   s_i[8][PPW];
    __shared__ int   s_j[8][PPW];
    __shared__ float s_a[8][PPW];

    int warp = threadIdx.x >> 5;
    int lane = threadIdx.x & 31;
    long long w = (long long)blockIdx.x * 8 + warp;
    long long start = w * PPW;
    if (start >= n_pairs) return;
    int cnt = (int)min((long long)PPW, (long long)n_pairs - start);

    // coalesced staging
    for (int t = lane; t < cnt; t += 32) {
        s_i[warp][t] = idx_i[start + t];
        s_j[warp][t] = idx_j[start + t];
        s_a[warp][t] = alpha[start + t];
    }
    __syncwarp();

    const float4* x4 = (const float4*)x;
    float4 acc = {0.f, 0.f, 0.f, 0.f};
    int cur = s_i[warp][0];

    for (int t = 0; t < cnt; t++) {
        int i = s_i[warp][t];
        if (i != cur) {
            if ((unsigned)cur < (unsigned)n_atoms)
                red_add_v4(&g_A[(size_t)cur * F + lane * 4], acc);
            acc.x = 0.f; acc.y = 0.f; acc.z = 0.f; acc.w = 0.f;
            cur = i;
        }
        int   j = s_j[warp][t];
        float a = s_a[warp][t];
        if ((unsigned)j < (unsigned)n_atoms) {
            float4 v = __ldg(&x4[(size_t)j * 32 + lane]);   // coalesced 512B row gather (L2 hit)
            acc.x = fmaf(a, v.x, acc.x);
            acc.y = fmaf(a, v.y, acc.y);
            acc.z = fmaf(a, v.z, acc.z);
            acc.w = fmaf(a, v.w, acc.w);
        }
    }
    if ((unsigned)cur < (unsigned)n_atoms)
        red_add_v4(&g_A[(size_t)cur * F + lane * 4], acc);
}

// ---------------------------------------------------------------------------
// kernel 3: GEMM  Y[M,128] = A[M,128] @ W^T   (uses pre-transposed g_WT)
// Block: 256 threads, 64 rows x 128 cols per block.
// Thread (rowT=tid>>5, colT=tid&31) computes 8 rows x 4 cols with fma.rn.f32x2.
// A-side SMEM reads are warp-uniform broadcasts; B-side LDS.128 conflict-free.
// ---------------------------------------------------------------------------
__global__ void gemm_kernel(float* __restrict__ Y, int M) {
    extern __shared__ float smem[];
    float (*As)[F] = (float (*)[F])smem;              // 64 x 128  (32 KB)
    float (*Ws)[F] = (float (*)[F])(smem + 64 * F);   // 128 x 128 (64 KB), k-major

    int tid = threadIdx.x;
    int m0 = blockIdx.x * 64;

    const float4* A4  = (const float4*)g_A;
    const float4* WT4 = (const float4*)g_WT;

    // load W^T tile (k-major), coalesced, conflict-free
    #pragma unroll
    for (int idx = tid; idx < F * 32; idx += 256)
        ((float4*)Ws)[idx] = WT4[idx];

    // load A tile, coalesced, conflict-free stores
    #pragma unroll
    for (int idx = tid; idx < 64 * 32; idx += 256) {
        int m  = idx >> 5;
        int k4 = idx & 31;
        int gm = m0 + m;
        float4 v = {0.f, 0.f, 0.f, 0.f};
        if (gm < M) v = A4[(size_t)gm * 32 + k4];
        *(float4*)&As[m][k4 * 4] = v;
    }
    __syncthreads();

    int rowT = tid >> 5;
    int colT = tid & 31;
    int rb = rowT * 8;
    int cb = colT * 4;

    u64 acc0[8], acc1[8];
    u64 z = pack2(0.f, 0.f);
    #pragma unroll
    for (int r = 0; r < 8; r++) { acc0[r] = z; acc1[r] = z; }

    #pragma unroll 4
    for (int k = 0; k < F; k++) {
        float4 bv = *(const float4*)&Ws[k][cb];       // LDS.128, conflict-free
        u64 b01 = pack2(bv.x, bv.y);
        u64 b23 = pack2(bv.z, bv.w);
        #pragma unroll
        for (int r = 0; r < 8; r++) {
            float a = As[rb + r][k];                  // warp-uniform broadcast
            u64 a2 = pack2(a, a);
            acc0[r] = fma2(a2, b01, acc0[r]);
            acc1[r] = fma2(a2, b23, acc1[r]);
        }
    }

    float4* Y4 = (float4*)Y;
    #pragma unroll
    for (int r = 0; r < 8; r++) {
        int gm = m0 + rb + r;
        if (gm < M) {
            float4 o;
            unpack2(acc0[r], o.x, o.y);
            unpack2(acc1[r], o.z, o.w);
            Y4[(size_t)gm * 32 + colT] = o;
        }
    }
}

// ---------------------------------------------------------------------------
// launcher
// ---------------------------------------------------------------------------
extern "C" void kernel_launch(void* const* d_in, const int* in_sizes, int n_in,
                              void* d_out, int out_size) {
    const float* x     = (const float*)d_in[0];
    const float* alpha = (const float*)d_in[1];
    const int*   idx_i = (const int*)d_in[2];
    const int*   idx_j = (const int*)d_in[3];
    const float* W     = (const float*)d_in[4];
    float*       Y     = (float*)d_out;

    int n_atoms = in_sizes[0] / F;
    int n_pairs = in_sizes[1];

    // 0: zero scatter accumulator
    zero_kernel<<<512, 256>>>(n_atoms * 32);

    // 1: transpose W (tiny)
    transpose_kernel<<<(F * F + 255) / 256, 256>>>(W);

    // 2: scatter alpha * x[idx_j] -> g_A (segment-run accumulation + red.v4)
    int nwarps  = (n_pairs + PPW - 1) / PPW;
    int nblocks = (nwarps + 7) / 8;
    scatter_kernel<<<nblocks, 256>>>(x, alpha, idx_i, idx_j, n_pairs, n_atoms);

    // 3: Y = g_A @ W^T
    cudaFuncSetAttribute(gemm_kernel, cudaFuncAttributeMaxDynamicSharedMemorySize, 98304);
    gemm_kernel<<<(n_atoms + 63) / 64, 256, 98304>>>(Y, n_atoms);
}